// round 12
// baseline (speedup 1.0000x reference)
#include <cuda_runtime.h>
#include <cuda_fp16.h>
#include <cuda_bf16.h>
#include <cstdint>

#define NNODES 50000
#define NEDGES 800000
#define DF 96
#define NF4 24

// ---------------- scratch ------------------------------------------------------
__device__ __align__(16) float g_deg[NNODES];
__device__ __align__(16) float g_dis[NNODES];
__device__ __align__(16) int   g_cnt[NNODES];        // in-degree / fill cursor
__device__ __align__(16) int   g_rowptr[NNODES + 1]; // CSR by destination
__device__ __align__(16) int   g_csr_src[NEDGES];
__device__ __align__(16) float g_csr_w[NEDGES];
__device__ __align__(16) float g_T1[NNODES * DF];
__device__ __align__(16) float g_T2[NNODES * DF];
__device__ __align__(16) __half g_xh[NNODES * DF];   // fp16 gather copies
__device__ __align__(16) __half g_T1h[NNODES * DF];
__device__ __align__(16) float g_Wc[3 * DF * DF];    // [288][96]
__device__ __align__(16) float g_stats[2 * DF];
__device__ __align__(16) float g_ab[2 * DF];

// grid-scan scratch
#define SBLK 512
#define NBLK ((NNODES + SBLK - 1) / SBLK)   // 98
__device__ int g_bsum[NBLK];
__device__ int g_boff[NBLK];

// bit-cast helper (replaces missing __half2_as_uint intrinsic)
__device__ __forceinline__ unsigned h2_as_u32(__half2 h) {
    return *reinterpret_cast<unsigned*>(&h);
}

// ---------------- init ---------------------------------------------------------
__global__ void k_init() {
    int stride = gridDim.x * blockDim.x;
    int t0 = blockIdx.x * blockDim.x + threadIdx.x;
    for (int i = t0; i < NNODES; i += stride) { g_deg[i] = 0.f; g_cnt[i] = 0; }
    if (t0 < 2 * DF) g_stats[t0] = 0.f;
}

__global__ void k_count(const int* __restrict__ ei) {
    int e = blockIdx.x * blockDim.x + threadIdx.x;
    if (e >= NEDGES) return;
    int r = ei[e], c = ei[NEDGES + e];
    if (r != c) {
        atomicAdd(&g_deg[r], 1.0f);
        atomicAdd(&g_cnt[c], 1);
    }
}

__global__ void k_dis() {
    int i = blockIdx.x * blockDim.x + threadIdx.x;
    if (i >= NNODES) return;
    float d = g_deg[i];
    g_dis[i] = (d > 0.f) ? rsqrtf(d) : 0.f;
}

// x -> fp16 copy (gather source for pull phase 0); 8 floats per thread
__global__ void k_xhalf(const float* __restrict__ x) {
    int t = blockIdx.x * blockDim.x + threadIdx.x;
    if (t >= NNODES * DF / 8) return;
    const float4* xp = reinterpret_cast<const float4*>(x);
    float4 a = xp[2 * t], b = xp[2 * t + 1];
    uint4 h;
    h.x = h2_as_u32(__floats2half2_rn(a.x, a.y));
    h.y = h2_as_u32(__floats2half2_rn(a.z, a.w));
    h.z = h2_as_u32(__floats2half2_rn(b.x, b.y));
    h.w = h2_as_u32(__floats2half2_rn(b.z, b.w));
    reinterpret_cast<uint4*>(g_xh)[t] = h;
}

// ---------------- decoupled grid scan ------------------------------------------
__global__ __launch_bounds__(SBLK) void k_scan_blk() {
    __shared__ int wsum[SBLK / 32];
    int i = blockIdx.x * SBLK + threadIdx.x;
    int lane = threadIdx.x & 31;
    int wid = threadIdx.x >> 5;
    int v = (i < NNODES) ? g_cnt[i] : 0;

    int incl = v;
#pragma unroll
    for (int d = 1; d < 32; d <<= 1) {
        int t = __shfl_up_sync(0xffffffffu, incl, d);
        if (lane >= d) incl += t;
    }
    if (lane == 31) wsum[wid] = incl;
    __syncthreads();
    if (wid == 0) {
        int ws = (lane < SBLK / 32) ? wsum[lane] : 0;
        int wincl = ws;
#pragma unroll
        for (int d = 1; d < SBLK / 32; d <<= 1) {
            int t = __shfl_up_sync(0xffffffffu, wincl, d);
            if (lane >= d) wincl += t;
        }
        if (lane < SBLK / 32) wsum[lane] = wincl - ws;
        if (lane == SBLK / 32 - 1) g_bsum[blockIdx.x] = wincl;
    }
    __syncthreads();
    if (i < NNODES) g_rowptr[i] = (incl - v) + wsum[wid];
}

__global__ void k_scan_top() {
    __shared__ int wsum[4];
    int t = threadIdx.x;          // 128 threads
    int lane = t & 31;
    int wid = t >> 5;
    int v = (t < NBLK) ? g_bsum[t] : 0;
    int incl = v;
#pragma unroll
    for (int d = 1; d < 32; d <<= 1) {
        int x = __shfl_up_sync(0xffffffffu, incl, d);
        if (lane >= d) incl += x;
    }
    if (lane == 31) wsum[wid] = incl;
    __syncthreads();
    if (wid == 0 && lane < 4) {
        int ws = wsum[lane];
        int wincl = ws;
#pragma unroll
        for (int d = 1; d < 4; d <<= 1) {
            int x = __shfl_up_sync(0x0000000fu, wincl, d);
            if (lane >= d) wincl += x;
        }
        wsum[lane] = wincl - ws;
        if (lane == 3) g_rowptr[NNODES] = wincl;
    }
    __syncthreads();
    if (t < NBLK) g_boff[t] = (incl - v) + wsum[wid];
}

__global__ void k_scan_add() {
    int i = blockIdx.x * blockDim.x + threadIdx.x;
    if (i >= NNODES) return;
    g_rowptr[i] += g_boff[i >> 9];   // SBLK = 512
    g_cnt[i] = 0;
}

__global__ void k_fill(const int* __restrict__ ei) {
    int e = blockIdx.x * blockDim.x + threadIdx.x;
    if (e >= NEDGES) return;
    int r = ei[e], c = ei[NEDGES + e];
    if (r == c) return;
    int pos = g_rowptr[c] + atomicAdd(&g_cnt[c], 1);
    g_csr_src[pos] = r;
    g_csr_w[pos] = -g_dis[r] * g_dis[c];
}

// ---------------- pull-mode propagation (fp16 gather, fp32 accumulate) ----------
// One warp per destination node. Lane owns features {2*lane, 2*lane+1, 64+lane}:
// one half2 load (128B warp wavefront) + one scalar half (64B) per edge.
// phase 0: T1 = L x   (writes fp32 T1 for GEMM + fp16 T1h for phase 1)
// phase 1: T2 = L T1h (writes fp32 T2)
__global__ __launch_bounds__(256) void k_pull(int phase) {
    const __half* src = (phase == 0) ? g_xh : g_T1h;
    int nd = (blockIdx.x * blockDim.x + threadIdx.x) >> 5;
    int lane = threadIdx.x & 31;
    if (nd >= NNODES) return;
    int s = g_rowptr[nd], e = g_rowptr[nd + 1];
    float a0 = 0.f, a1 = 0.f, a2 = 0.f;
    int i = s;
    for (; i + 4 <= e; i += 4) {
        int r0 = g_csr_src[i],     r1 = g_csr_src[i + 1];
        int r2 = g_csr_src[i + 2], r3 = g_csr_src[i + 3];
        float w0 = g_csr_w[i],     w1 = g_csr_w[i + 1];
        float w2 = g_csr_w[i + 2], w3 = g_csr_w[i + 3];
        __half2 h0 = reinterpret_cast<const __half2*>(src + r0 * DF)[lane];
        __half2 h1 = reinterpret_cast<const __half2*>(src + r1 * DF)[lane];
        __half2 h2 = reinterpret_cast<const __half2*>(src + r2 * DF)[lane];
        __half2 h3 = reinterpret_cast<const __half2*>(src + r3 * DF)[lane];
        __half s0 = src[r0 * DF + 64 + lane];
        __half s1 = src[r1 * DF + 64 + lane];
        __half s2 = src[r2 * DF + 64 + lane];
        __half s3 = src[r3 * DF + 64 + lane];
        float2 f0 = __half22float2(h0), f1 = __half22float2(h1);
        float2 f2 = __half22float2(h2), f3 = __half22float2(h3);
        a0 += w0 * f0.x + w1 * f1.x + w2 * f2.x + w3 * f3.x;
        a1 += w0 * f0.y + w1 * f1.y + w2 * f2.y + w3 * f3.y;
        a2 += w0 * __half2float(s0) + w1 * __half2float(s1)
            + w2 * __half2float(s2) + w3 * __half2float(s3);
    }
    for (; i < e; i++) {
        int r = g_csr_src[i];
        float ww = g_csr_w[i];
        __half2 h = reinterpret_cast<const __half2*>(src + r * DF)[lane];
        __half sc = src[r * DF + 64 + lane];
        float2 f = __half22float2(h);
        a0 += ww * f.x;
        a1 += ww * f.y;
        a2 += ww * __half2float(sc);
    }
    float* dstf = (phase == 0) ? g_T1 : g_T2;
    reinterpret_cast<float2*>(dstf + nd * DF)[lane] = make_float2(a0, a1);
    dstf[nd * DF + 64 + lane] = a2;
    if (phase == 0) {
        reinterpret_cast<__half2*>(g_T1h + nd * DF)[lane] =
            __floats2half2_rn(a0, a1);
        g_T1h[nd * DF + 64 + lane] = __float2half_rn(a2);
    }
}

// ---------------- combined weights ---------------------------------------------
__global__ void k_wprep(const float* __restrict__ W) {
    int idx = blockIdx.x * blockDim.x + threadIdx.x;
    if (idx >= 3 * DF * DF) return;
    int kg = idx / DF, c = idx - kg * DF;
    int m = kg / DF, i = kg - m * DF;
    float v;
    if (m == 0)      v = W[i * DF + c] - W[2 * DF * DF + i * DF + c];
    else if (m == 1) v = W[DF * DF + i * DF + c];
    else             v = 2.f * W[2 * DF * DF + i * DF + c];
    g_Wc[idx] = v;
}

// ---------------- FFMA2 helpers ------------------------------------------------
typedef unsigned long long u64t;
__device__ __forceinline__ u64t dup2(float v) {
    u64t r;
    asm("mov.b64 %0, {%1, %1};" : "=l"(r) : "f"(v));
    return r;
}
__device__ __forceinline__ void ffma2(u64t& d, u64t a, u64t b) {
    asm volatile("fma.rn.f32x2 %0, %1, %2, %0;" : "+l"(d) : "l"(a), "l"(b));
}
__device__ __forceinline__ float2 unpk(u64t v) {
    float2 f;
    asm("mov.b64 {%0, %1}, %2;" : "=f"(f.x), "=f"(f.y) : "l"(v));
    return f;
}

// ---------------- fused GEMM + BN-stats (known-good R6 version) -----------------
#define BM 128
#define BK 16
__global__ __launch_bounds__(256) void k_gemm(const float* __restrict__ x,
                                              float* __restrict__ out) {
    __shared__ u64t  As2[BK][BM];      // 16 KB, dup pairs
    __shared__ float Bs[BK][DF];       // 6 KB
    __shared__ float s_sum[DF], s_sq[DF];

    int tid = threadIdx.x;
    int tr = tid >> 3;          // 0..31 -> rows tr*4 .. +3
    int tc = tid & 7;           // 0..7  -> cols tc*12 .. +11
    int row0 = blockIdx.x * BM;

    if (tid < DF) { s_sum[tid] = 0.f; s_sq[tid] = 0.f; }

    u64t acc[4][6];
#pragma unroll
    for (int i = 0; i < 4; i++)
#pragma unroll
        for (int j = 0; j < 6; j++) acc[i][j] = 0ull;

    const float* bases[3] = { x, g_T1, g_T2 };

    int a_row = tid & 127;
    int a_half = tid >> 7;      // 0 or 1
    int b_kk = tid >> 4;
    int b_c0 = (tid & 15) * 6;

    for (int kc = 0; kc < 18; kc++) {
        const float* A = bases[kc / 6];
        int klocal = (kc % 6) * BK;
        int r = row0 + a_row;

#pragma unroll
        for (int q = 0; q < 2; q++) {
            int kq = (a_half * 2 + q) * 4;
            float4 av = make_float4(0.f, 0.f, 0.f, 0.f);
            if (r < NNODES)
                av = *reinterpret_cast<const float4*>(A + r * DF + klocal + kq);
            As2[kq + 0][a_row] = dup2(av.x);
            As2[kq + 1][a_row] = dup2(av.y);
            As2[kq + 2][a_row] = dup2(av.z);
            As2[kq + 3][a_row] = dup2(av.w);
        }
        {
            const float* Bp = g_Wc + (kc * BK + b_kk) * DF + b_c0;
#pragma unroll
            for (int j = 0; j < 6; j++) Bs[b_kk][b_c0 + j] = Bp[j];
        }
        __syncthreads();

#pragma unroll
        for (int kk = 0; kk < BK; kk++) {
            const ulonglong2* pa =
                reinterpret_cast<const ulonglong2*>(&As2[kk][tr * 4]);
            ulonglong2 A0 = pa[0], A1 = pa[1];
            const ulonglong2* pb =
                reinterpret_cast<const ulonglong2*>(&Bs[kk][tc * 12]);
            ulonglong2 B0 = pb[0], B1 = pb[1], B2 = pb[2];
            u64t a[4] = { A0.x, A0.y, A1.x, A1.y };
            u64t b[6] = { B0.x, B0.y, B1.x, B1.y, B2.x, B2.y };
#pragma unroll
            for (int i = 0; i < 4; i++)
#pragma unroll
                for (int j = 0; j < 6; j++) ffma2(acc[i][j], a[i], b[j]);
        }
        __syncthreads();
    }

    // epilogue: store + per-column stats (invalid rows hold exact zeros)
    float csum[12], csq[12];
#pragma unroll
    for (int j = 0; j < 12; j++) { csum[j] = 0.f; csq[j] = 0.f; }

#pragma unroll
    for (int i = 0; i < 4; i++) {
        int r = row0 + tr * 4 + i;
        float v[12];
#pragma unroll
        for (int j = 0; j < 6; j++) {
            float2 f = unpk(acc[i][j]);
            v[2 * j] = f.x;
            v[2 * j + 1] = f.y;
        }
#pragma unroll
        for (int j = 0; j < 12; j++) { csum[j] += v[j]; csq[j] += v[j] * v[j]; }
        if (r < NNODES) {
            float* op = out + r * DF + tc * 12;
#pragma unroll
            for (int j = 0; j < 3; j++)
                reinterpret_cast<float4*>(op)[j] =
                    make_float4(v[4 * j], v[4 * j + 1], v[4 * j + 2], v[4 * j + 3]);
        }
    }

#pragma unroll
    for (int j = 0; j < 12; j++) {
        csum[j] += __shfl_xor_sync(0xffffffffu, csum[j], 8);
        csum[j] += __shfl_xor_sync(0xffffffffu, csum[j], 16);
        csq[j]  += __shfl_xor_sync(0xffffffffu, csq[j], 8);
        csq[j]  += __shfl_xor_sync(0xffffffffu, csq[j], 16);
    }
    __syncthreads();
    if ((threadIdx.x & 31) < 8) {
#pragma unroll
        for (int j = 0; j < 12; j++) {
            atomicAdd(&s_sum[tc * 12 + j], csum[j]);
            atomicAdd(&s_sq[tc * 12 + j], csq[j]);
        }
    }
    __syncthreads();
    if (tid < DF) {
        atomicAdd(&g_stats[tid], s_sum[tid]);
        atomicAdd(&g_stats[DF + tid], s_sq[tid]);
    }
}

// ---------------- BN finalize + apply ------------------------------------------
__global__ void k_bnfin(const float* __restrict__ gamma,
                        const float* __restrict__ beta) {
    int c = threadIdx.x;
    if (c >= DF) return;
    float mean = g_stats[c] * (1.0f / NNODES);
    float var  = g_stats[DF + c] * (1.0f / NNODES) - mean * mean;
    float a = gamma[c] * rsqrtf(var + 1e-5f);
    g_ab[c] = a;
    g_ab[DF + c] = beta[c] - mean * a;
}

__global__ void k_bnapply(float* __restrict__ out) {
    int t = blockIdx.x * blockDim.x + threadIdx.x;
    if (t >= NNODES * NF4) return;
    int j = t % NF4;
    int c0 = j * 4;
    float4 v = reinterpret_cast<float4*>(out)[t];
    v.x = v.x * g_ab[c0 + 0] + g_ab[DF + c0 + 0];
    v.y = v.y * g_ab[c0 + 1] + g_ab[DF + c0 + 1];
    v.z = v.z * g_ab[c0 + 2] + g_ab[DF + c0 + 2];
    v.w = v.w * g_ab[c0 + 3] + g_ab[DF + c0 + 3];
    reinterpret_cast<float4*>(out)[t] = v;
}

// ---------------- launch -------------------------------------------------------
extern "C" void kernel_launch(void* const* d_in, const int* in_sizes, int n_in,
                              void* d_out, int out_size) {
    const float* x     = (const float*)d_in[0];
    const int*   ei    = (const int*)  d_in[1];
    const float* W     = (const float*)d_in[2];
    const float* gamma = (const float*)d_in[4];
    const float* beta  = (const float*)d_in[5];
    float* out = (float*)d_out;

    k_init <<<128, 512>>>();
    k_count<<<(NEDGES + 255) / 256, 256>>>(ei);
    k_dis  <<<(NNODES + 255) / 256, 256>>>();
    k_xhalf<<<(NNODES * DF / 8 + 255) / 256, 256>>>(x);

    k_scan_blk<<<NBLK, SBLK>>>();
    k_scan_top<<<1, 128>>>();
    k_scan_add<<<(NNODES + 255) / 256, 256>>>();

    k_fill <<<(NEDGES + 255) / 256, 256>>>(ei);

    const int pullBlocks = (NNODES * 32 + 255) / 256;
    k_pull<<<pullBlocks, 256>>>(0);   // T1 = L x   (fp16 gather)
    k_pull<<<pullBlocks, 256>>>(1);   // T2 = L T1  (fp16 gather)

    k_wprep<<<(3 * DF * DF + 255) / 256, 256>>>(W);
    k_gemm <<<(NNODES + BM - 1) / BM, 256>>>(x, out);   // + fused BN stats

    k_bnfin  <<<1, DF>>>(gamma, beta);
    k_bnapply<<<(NNODES * NF4 + 255) / 256, 256>>>(out);
}

// round 14
// speedup vs baseline: 1.0102x; 1.0102x over previous
#include <cuda_runtime.h>
#include <cuda_bf16.h>
#include <cstdint>

#define NNODES 50000
#define NEDGES 800000
#define DF 96
#define NF4 24

// ---------------- scratch ------------------------------------------------------
__device__ __align__(16) float g_deg[NNODES];
__device__ __align__(16) float g_dis[NNODES];
__device__ __align__(16) int   g_cnt[NNODES];        // in-degree / fill cursor
__device__ __align__(16) int   g_rowptr[NNODES + 1]; // CSR by destination
__device__ __align__(16) int   g_csr_src[NEDGES];
__device__ __align__(16) float g_csr_w[NEDGES];
__device__ __align__(16) float g_T1[NNODES * DF];
__device__ __align__(16) float g_T2[NNODES * DF];
__device__ __align__(16) float g_Wc[3 * DF * DF];    // [288][96]
__device__ __align__(16) float g_stats[2 * DF];
__device__ __align__(16) float g_ab[2 * DF];

// grid-scan scratch
#define SBLK 512
#define NBLK ((NNODES + SBLK - 1) / SBLK)   // 98
__device__ int g_bsum[NBLK];
__device__ int g_boff[NBLK];

// ---------------- init ---------------------------------------------------------
__global__ void k_init() {
    int stride = gridDim.x * blockDim.x;
    int t0 = blockIdx.x * blockDim.x + threadIdx.x;
    for (int i = t0; i < NNODES; i += stride) { g_deg[i] = 0.f; g_cnt[i] = 0; }
    if (t0 < 2 * DF) g_stats[t0] = 0.f;
}

__global__ void k_count(const int* __restrict__ ei) {
    int e = blockIdx.x * blockDim.x + threadIdx.x;
    if (e >= NEDGES) return;
    int r = ei[e], c = ei[NEDGES + e];
    if (r != c) {
        atomicAdd(&g_deg[r], 1.0f);
        atomicAdd(&g_cnt[c], 1);
    }
}

__global__ void k_dis() {
    int i = blockIdx.x * blockDim.x + threadIdx.x;
    if (i >= NNODES) return;
    float d = g_deg[i];
    g_dis[i] = (d > 0.f) ? rsqrtf(d) : 0.f;
}

// ---------------- decoupled grid scan ------------------------------------------
__global__ __launch_bounds__(SBLK) void k_scan_blk() {
    __shared__ int wsum[SBLK / 32];
    int i = blockIdx.x * SBLK + threadIdx.x;
    int lane = threadIdx.x & 31;
    int wid = threadIdx.x >> 5;
    int v = (i < NNODES) ? g_cnt[i] : 0;

    int incl = v;
#pragma unroll
    for (int d = 1; d < 32; d <<= 1) {
        int t = __shfl_up_sync(0xffffffffu, incl, d);
        if (lane >= d) incl += t;
    }
    if (lane == 31) wsum[wid] = incl;
    __syncthreads();
    if (wid == 0) {
        int ws = (lane < SBLK / 32) ? wsum[lane] : 0;
        int wincl = ws;
#pragma unroll
        for (int d = 1; d < SBLK / 32; d <<= 1) {
            int t = __shfl_up_sync(0xffffffffu, wincl, d);
            if (lane >= d) wincl += t;
        }
        if (lane < SBLK / 32) wsum[lane] = wincl - ws;
        if (lane == SBLK / 32 - 1) g_bsum[blockIdx.x] = wincl;
    }
    __syncthreads();
    if (i < NNODES) g_rowptr[i] = (incl - v) + wsum[wid];
}

__global__ void k_scan_top() {
    __shared__ int wsum[4];
    int t = threadIdx.x;          // 128 threads
    int lane = t & 31;
    int wid = t >> 5;
    int v = (t < NBLK) ? g_bsum[t] : 0;
    int incl = v;
#pragma unroll
    for (int d = 1; d < 32; d <<= 1) {
        int x = __shfl_up_sync(0xffffffffu, incl, d);
        if (lane >= d) incl += x;
    }
    if (lane == 31) wsum[wid] = incl;
    __syncthreads();
    if (wid == 0 && lane < 4) {
        int ws = wsum[lane];
        int wincl = ws;
#pragma unroll
        for (int d = 1; d < 4; d <<= 1) {
            int x = __shfl_up_sync(0x0000000fu, wincl, d);
            if (lane >= d) wincl += x;
        }
        wsum[lane] = wincl - ws;
        if (lane == 3) g_rowptr[NNODES] = wincl;
    }
    __syncthreads();
    if (t < NBLK) g_boff[t] = (incl - v) + wsum[wid];
}

__global__ void k_scan_add() {
    int i = blockIdx.x * blockDim.x + threadIdx.x;
    if (i >= NNODES) return;
    g_rowptr[i] += g_boff[i >> 9];   // SBLK = 512
    g_cnt[i] = 0;
}

__global__ void k_fill(const int* __restrict__ ei) {
    int e = blockIdx.x * blockDim.x + threadIdx.x;
    if (e >= NEDGES) return;
    int r = ei[e], c = ei[NEDGES + e];
    if (r == c) return;
    int pos = g_rowptr[c] + atomicAdd(&g_cnt[c], 1);
    g_csr_src[pos] = r;
    g_csr_w[pos] = -g_dis[r] * g_dis[c];
}

// ---------------- pull-mode propagation (vector gather, fp32) -------------------
// One warp per destination node. Lanes 0..23 each own one float4 chunk of the
// 96-float row -> ONE LDG.128 per edge (3 wavefronts) instead of 3x LDG.32.
// Lanes 24..31 duplicate chunks 16..23 (same sectors, no divergence, no extra
// traffic); only lanes 0..23 store. Unroll-4 gives 4 gathers in flight.
// phase 0: T1 = L x     phase 1: T2 = L T1   (selected device-side)
__global__ __launch_bounds__(256) void k_pull(int phase,
                                              const float* __restrict__ x) {
    const float* src = (phase == 0) ? x : g_T1;
    float* dst = (phase == 0) ? g_T1 : g_T2;
    int nd = (blockIdx.x * blockDim.x + threadIdx.x) >> 5;
    int lane = threadIdx.x & 31;
    if (nd >= NNODES) return;
    int s = g_rowptr[nd], e = g_rowptr[nd + 1];
    int ch = (lane < 24) ? lane : (lane - 8);   // tail lanes duplicate
    float a0 = 0.f, a1 = 0.f, a2 = 0.f, a3 = 0.f;
    int i = s;
    for (; i + 4 <= e; i += 4) {
        int r0 = g_csr_src[i],     r1 = g_csr_src[i + 1];
        int r2 = g_csr_src[i + 2], r3 = g_csr_src[i + 3];
        float w0 = g_csr_w[i],     w1 = g_csr_w[i + 1];
        float w2 = g_csr_w[i + 2], w3 = g_csr_w[i + 3];
        float4 v0 = reinterpret_cast<const float4*>(src + r0 * DF)[ch];
        float4 v1 = reinterpret_cast<const float4*>(src + r1 * DF)[ch];
        float4 v2 = reinterpret_cast<const float4*>(src + r2 * DF)[ch];
        float4 v3 = reinterpret_cast<const float4*>(src + r3 * DF)[ch];
        a0 += w0 * v0.x + w1 * v1.x + w2 * v2.x + w3 * v3.x;
        a1 += w0 * v0.y + w1 * v1.y + w2 * v2.y + w3 * v3.y;
        a2 += w0 * v0.z + w1 * v1.z + w2 * v2.z + w3 * v3.z;
        a3 += w0 * v0.w + w1 * v1.w + w2 * v2.w + w3 * v3.w;
    }
    for (; i < e; i++) {
        int r = g_csr_src[i];
        float ww = g_csr_w[i];
        float4 v = reinterpret_cast<const float4*>(src + r * DF)[ch];
        a0 += ww * v.x;
        a1 += ww * v.y;
        a2 += ww * v.z;
        a3 += ww * v.w;
    }
    if (lane < 24)
        reinterpret_cast<float4*>(dst + nd * DF)[lane] =
            make_float4(a0, a1, a2, a3);
}

// ---------------- combined weights ---------------------------------------------
__global__ void k_wprep(const float* __restrict__ W) {
    int idx = blockIdx.x * blockDim.x + threadIdx.x;
    if (idx >= 3 * DF * DF) return;
    int kg = idx / DF, c = idx - kg * DF;
    int m = kg / DF, i = kg - m * DF;
    float v;
    if (m == 0)      v = W[i * DF + c] - W[2 * DF * DF + i * DF + c];
    else if (m == 1) v = W[DF * DF + i * DF + c];
    else             v = 2.f * W[2 * DF * DF + i * DF + c];
    g_Wc[idx] = v;
}

// ---------------- FFMA2 helpers ------------------------------------------------
typedef unsigned long long u64t;
__device__ __forceinline__ u64t dup2(float v) {
    u64t r;
    asm("mov.b64 %0, {%1, %1};" : "=l"(r) : "f"(v));
    return r;
}
__device__ __forceinline__ void ffma2(u64t& d, u64t a, u64t b) {
    asm volatile("fma.rn.f32x2 %0, %1, %2, %0;" : "+l"(d) : "l"(a), "l"(b));
}
__device__ __forceinline__ float2 unpk(u64t v) {
    float2 f;
    asm("mov.b64 {%0, %1}, %2;" : "=f"(f.x), "=f"(f.y) : "l"(v));
    return f;
}

// ---------------- fused GEMM + BN-stats (known-good R6 version) -----------------
#define BM 128
#define BK 16
__global__ __launch_bounds__(256) void k_gemm(const float* __restrict__ x,
                                              float* __restrict__ out) {
    __shared__ u64t  As2[BK][BM];      // 16 KB, dup pairs
    __shared__ float Bs[BK][DF];       // 6 KB
    __shared__ float s_sum[DF], s_sq[DF];

    int tid = threadIdx.x;
    int tr = tid >> 3;          // 0..31 -> rows tr*4 .. +3
    int tc = tid & 7;           // 0..7  -> cols tc*12 .. +11
    int row0 = blockIdx.x * BM;

    if (tid < DF) { s_sum[tid] = 0.f; s_sq[tid] = 0.f; }

    u64t acc[4][6];
#pragma unroll
    for (int i = 0; i < 4; i++)
#pragma unroll
        for (int j = 0; j < 6; j++) acc[i][j] = 0ull;

    const float* bases[3] = { x, g_T1, g_T2 };

    int a_row = tid & 127;
    int a_half = tid >> 7;      // 0 or 1
    int b_kk = tid >> 4;
    int b_c0 = (tid & 15) * 6;

    for (int kc = 0; kc < 18; kc++) {
        const float* A = bases[kc / 6];
        int klocal = (kc % 6) * BK;
        int r = row0 + a_row;

#pragma unroll
        for (int q = 0; q < 2; q++) {
            int kq = (a_half * 2 + q) * 4;
            float4 av = make_float4(0.f, 0.f, 0.f, 0.f);
            if (r < NNODES)
                av = *reinterpret_cast<const float4*>(A + r * DF + klocal + kq);
            As2[kq + 0][a_row] = dup2(av.x);
            As2[kq + 1][a_row] = dup2(av.y);
            As2[kq + 2][a_row] = dup2(av.z);
            As2[kq + 3][a_row] = dup2(av.w);
        }
        {
            const float* Bp = g_Wc + (kc * BK + b_kk) * DF + b_c0;
#pragma unroll
            for (int j = 0; j < 6; j++) Bs[b_kk][b_c0 + j] = Bp[j];
        }
        __syncthreads();

#pragma unroll
        for (int kk = 0; kk < BK; kk++) {
            const ulonglong2* pa =
                reinterpret_cast<const ulonglong2*>(&As2[kk][tr * 4]);
            ulonglong2 A0 = pa[0], A1 = pa[1];
            const ulonglong2* pb =
                reinterpret_cast<const ulonglong2*>(&Bs[kk][tc * 12]);
            ulonglong2 B0 = pb[0], B1 = pb[1], B2 = pb[2];
            u64t a[4] = { A0.x, A0.y, A1.x, A1.y };
            u64t b[6] = { B0.x, B0.y, B1.x, B1.y, B2.x, B2.y };
#pragma unroll
            for (int i = 0; i < 4; i++)
#pragma unroll
                for (int j = 0; j < 6; j++) ffma2(acc[i][j], a[i], b[j]);
        }
        __syncthreads();
    }

    // epilogue: store + per-column stats (invalid rows hold exact zeros)
    float csum[12], csq[12];
#pragma unroll
    for (int j = 0; j < 12; j++) { csum[j] = 0.f; csq[j] = 0.f; }

#pragma unroll
    for (int i = 0; i < 4; i++) {
        int r = row0 + tr * 4 + i;
        float v[12];
#pragma unroll
        for (int j = 0; j < 6; j++) {
            float2 f = unpk(acc[i][j]);
            v[2 * j] = f.x;
            v[2 * j + 1] = f.y;
        }
#pragma unroll
        for (int j = 0; j < 12; j++) { csum[j] += v[j]; csq[j] += v[j] * v[j]; }
        if (r < NNODES) {
            float* op = out + r * DF + tc * 12;
#pragma unroll
            for (int j = 0; j < 3; j++)
                reinterpret_cast<float4*>(op)[j] =
                    make_float4(v[4 * j], v[4 * j + 1], v[4 * j + 2], v[4 * j + 3]);
        }
    }

#pragma unroll
    for (int j = 0; j < 12; j++) {
        csum[j] += __shfl_xor_sync(0xffffffffu, csum[j], 8);
        csum[j] += __shfl_xor_sync(0xffffffffu, csum[j], 16);
        csq[j]  += __shfl_xor_sync(0xffffffffu, csq[j], 8);
        csq[j]  += __shfl_xor_sync(0xffffffffu, csq[j], 16);
    }
    __syncthreads();
    if ((threadIdx.x & 31) < 8) {
#pragma unroll
        for (int j = 0; j < 12; j++) {
            atomicAdd(&s_sum[tc * 12 + j], csum[j]);
            atomicAdd(&s_sq[tc * 12 + j], csq[j]);
        }
    }
    __syncthreads();
    if (tid < DF) {
        atomicAdd(&g_stats[tid], s_sum[tid]);
        atomicAdd(&g_stats[DF + tid], s_sq[tid]);
    }
}

// ---------------- BN finalize + apply ------------------------------------------
__global__ void k_bnfin(const float* __restrict__ gamma,
                        const float* __restrict__ beta) {
    int c = threadIdx.x;
    if (c >= DF) return;
    float mean = g_stats[c] * (1.0f / NNODES);
    float var  = g_stats[DF + c] * (1.0f / NNODES) - mean * mean;
    float a = gamma[c] * rsqrtf(var + 1e-5f);
    g_ab[c] = a;
    g_ab[DF + c] = beta[c] - mean * a;
}

__global__ void k_bnapply(float* __restrict__ out) {
    int t = blockIdx.x * blockDim.x + threadIdx.x;
    if (t >= NNODES * NF4) return;
    int j = t % NF4;
    int c0 = j * 4;
    float4 v = reinterpret_cast<float4*>(out)[t];
    v.x = v.x * g_ab[c0 + 0] + g_ab[DF + c0 + 0];
    v.y = v.y * g_ab[c0 + 1] + g_ab[DF + c0 + 1];
    v.z = v.z * g_ab[c0 + 2] + g_ab[DF + c0 + 2];
    v.w = v.w * g_ab[c0 + 3] + g_ab[DF + c0 + 3];
    reinterpret_cast<float4*>(out)[t] = v;
}

// ---------------- launch -------------------------------------------------------
extern "C" void kernel_launch(void* const* d_in, const int* in_sizes, int n_in,
                              void* d_out, int out_size) {
    const float* x     = (const float*)d_in[0];
    const int*   ei    = (const int*)  d_in[1];
    const float* W     = (const float*)d_in[2];
    const float* gamma = (const float*)d_in[4];
    const float* beta  = (const float*)d_in[5];
    float* out = (float*)d_out;

    k_init <<<128, 512>>>();
    k_count<<<(NEDGES + 255) / 256, 256>>>(ei);
    k_dis  <<<(NNODES + 255) / 256, 256>>>();

    k_scan_blk<<<NBLK, SBLK>>>();
    k_scan_top<<<1, 128>>>();
    k_scan_add<<<(NNODES + 255) / 256, 256>>>();

    k_fill <<<(NEDGES + 255) / 256, 256>>>(ei);

    const int pullBlocks = (NNODES * 32 + 255) / 256;
    k_pull<<<pullBlocks, 256>>>(0, x);   // T1 = L x
    k_pull<<<pullBlocks, 256>>>(1, x);   // T2 = L T1

    k_wprep<<<(3 * DF * DF + 255) / 256, 256>>>(W);
    k_gemm <<<(NNODES + BM - 1) / BM, 256>>>(x, out);   // + fused BN stats

    k_bnfin  <<<1, DF>>>(gamma, beta);
    k_bnapply<<<(NNODES * NF4 + 255) / 256, 256>>>(out);
}